// round 2
// baseline (speedup 1.0000x reference)
#include <cuda_runtime.h>
#include <math.h>

#define N 2048
#define IN_DIM 128
#define OUT_DIM 32
#define ROWS 4
#define NWARPS 8
#define TABSZ 2048

// Scratch (allocation-free rule: __device__ globals)
__device__ float g_z[N * OUT_DIM];
__device__ float g_src[N];
__device__ float g_dst[N];
__device__ float g_val[TABSZ + 1];

// ---------------------------------------------------------------------------
// Prep: z = feat @ W ; src = z @ a[:32] ; dst = z @ a[32:64]
// ---------------------------------------------------------------------------
__global__ void prep_kernel(const float* __restrict__ feat,
                            const float* __restrict__ a,
                            const float* __restrict__ W) {
    int i = blockIdx.x;      // row
    int k = threadIdx.x;     // out dim, 32 threads = 1 warp
    float acc = 0.f;
#pragma unroll
    for (int d = 0; d < IN_DIM; ++d)
        acc = fmaf(feat[i * IN_DIM + d], W[d * OUT_DIM + k], acc);
    g_z[i * OUT_DIM + k] = acc;

    float s = acc * a[k];
    float t = acc * a[OUT_DIM + k];
#pragma unroll
    for (int o = 16; o > 0; o >>= 1) {
        s += __shfl_xor_sync(0xffffffffu, s, o);
        t += __shfl_xor_sync(0xffffffffu, t, o);
    }
    if (k == 0) { g_src[i] = s; g_dst[i] = t; }
}

// ---------------------------------------------------------------------------
// Table: g_val[q] = sum_k a[2k]*sin(dt*f_k) + a[2k+1]*cos(dt*f_k),
//        dt = T - q/TABSZ. Same fp32 ops as reference -> same rounding.
// ---------------------------------------------------------------------------
__global__ void table_kernel(const float* __restrict__ a,
                             const int*   __restrict__ te,
                             const float* __restrict__ bf) {
    int q = blockIdx.x;        // 0..TABSZ
    int k = threadIdx.x;       // 0..31
    int ti = *te;
    float T = (ti > -1000000 && ti < 1000000) ? (float)ti : __int_as_float(ti);
    float tsv = (float)q / (float)TABSZ;
    float dt  = T - tsv;
    float th  = dt * bf[k];
    float v   = a[2 * k] * sinf(th) + a[2 * k + 1] * cosf(th);
#pragma unroll
    for (int o = 16; o > 0; o >>= 1)
        v += __shfl_xor_sync(0xffffffffu, v, o);
    if (k == 0) g_val[q] = v;
}

// ---------------------------------------------------------------------------
// Fused attention + softmax + att@z + residual + layernorm.
// One block = ROWS rows; 8 warps stripe over j in chunks of 4.
// e_time via smem table lerp (broadcast, conflict-free). No warp reductions
// in the hot loop. Masked pairs skipped exactly.
// ---------------------------------------------------------------------------
__global__ void __launch_bounds__(256)
attn_kernel(const int*   __restrict__ adj,
            const float* __restrict__ ts,
            const float* __restrict__ gamma,
            const float* __restrict__ beta,
            float*       __restrict__ out) {
    __shared__ float2 s_tab[TABSZ];
    __shared__ float sm_m[ROWS][NWARPS];
    __shared__ float sm_l[ROWS][NWARPS];
    __shared__ float sm_a[ROWS][NWARPS][OUT_DIM];

    const int i0   = blockIdx.x * ROWS;
    const int warp = threadIdx.x >> 5;
    const int lane = threadIdx.x & 31;

    // Preload interpolation table as (g[q], g[q+1]) pairs -> one LDS.64/lookup
    for (int q = threadIdx.x; q < TABSZ; q += 256)
        s_tab[q] = make_float2(g_val[q], g_val[q + 1]);
    __syncthreads();

    float src[ROWS];
#pragma unroll
    for (int r = 0; r < ROWS; ++r) src[r] = g_src[i0 + r];

    float m[ROWS], l[ROWS], acc[ROWS];
#pragma unroll
    for (int r = 0; r < ROWS; ++r) { m[r] = -1e30f; l[r] = 0.f; acc[r] = 0.f; }

    const int4*   adj4 = (const int4*)adj;
    const float4* ts4  = (const float4*)ts;
    const float4* dst4 = (const float4*)g_dst;
    const int NC = N / 4;

    for (int jc = warp; jc < NC; jc += NWARPS) {
        int4 am[ROWS];
        float4 tv[ROWS];
#pragma unroll
        for (int r = 0; r < ROWS; ++r) am[r] = adj4[(i0 + r) * NC + jc];
#pragma unroll
        for (int r = 0; r < ROWS; ++r) tv[r] = ts4[(i0 + r) * NC + jc];

        const int j0 = jc * 4;
        float zz[4];
#pragma unroll
        for (int u = 0; u < 4; ++u) zz[u] = g_z[(j0 + u) * OUT_DIM + lane];
        float4 djv = dst4[jc];
        const float dja[4] = {djv.x, djv.y, djv.z, djv.w};

#pragma unroll
        for (int u = 0; u < 4; ++u) {
#pragma unroll
            for (int r = 0; r < ROWS; ++r) {
                int   a_ = ((const int*)&am[r])[u];
                if (a_ > 0) {                       // warp-uniform branch
                    float t_ = ((const float*)&tv[r])[u];
                    float qf = t_ * (float)TABSZ;   // ts in [0,1)
                    int   qi = __float2int_rz(qf);
                    float fr = qf - (float)qi;
                    float2 tt = s_tab[qi];          // broadcast LDS.64
                    float g  = fmaf(fr, tt.y - tt.x, tt.x);
                    float e  = src[r] + dja[u] + g;
                    e = fmaxf(e, 0.05f * e);        // leaky relu
                    if (e > m[r]) {                 // rare, warp-uniform
                        float c = __expf(m[r] - e);
                        l[r] *= c; acc[r] *= c; m[r] = e;
                    }
                    float p = __expf(e - m[r]);
                    l[r] += p;
                    acc[r] = fmaf(p, zz[u], acc[r]);
                }
            }
        }
    }

    // Cross-warp combine
#pragma unroll
    for (int r = 0; r < ROWS; ++r) {
        if (lane == 0) { sm_m[r][warp] = m[r]; sm_l[r][warp] = l[r]; }
        sm_a[r][warp][lane] = acc[r];
    }
    __syncthreads();

    if (warp < ROWS) {
        const int r = warp;
        const int i = i0 + r;
        float M = -1e30f;
#pragma unroll
        for (int w = 0; w < NWARPS; ++w) M = fmaxf(M, sm_m[r][w]);
        float L = 0.f, A = 0.f;
#pragma unroll
        for (int w = 0; w < NWARPS; ++w) {
            float c = __expf(sm_m[r][w] - M);
            L += sm_l[r][w] * c;
            A  = fmaf(sm_a[r][w][lane], c, A);
        }
        float temp = A / L + g_z[i * OUT_DIM + lane];

        // LayerNorm over 32 dims (one warp)
        float mu = temp;
#pragma unroll
        for (int o = 16; o > 0; o >>= 1) mu += __shfl_xor_sync(0xffffffffu, mu, o);
        mu *= (1.0f / OUT_DIM);
        float d = temp - mu;
        float v = d * d;
#pragma unroll
        for (int o = 16; o > 0; o >>= 1) v += __shfl_xor_sync(0xffffffffu, v, o);
        v *= (1.0f / OUT_DIM);
        out[i * OUT_DIM + lane] = d * rsqrtf(v + 1e-6f) * gamma[lane] + beta[lane];
    }
}

// ---------------------------------------------------------------------------
extern "C" void kernel_launch(void* const* d_in, const int* in_sizes, int n_in,
                              void* d_out, int out_size) {
    const float* feat = (const float*)d_in[0];   // (2048,128) f32
    const int*   adj  = (const int*)  d_in[1];   // (2048,2048) i32
    const float* ts   = (const float*)d_in[2];   // (2048,2048) f32
    const float* a    = (const float*)d_in[3];   // (64,1) f32
    const int*   te   = (const int*)  d_in[4];   // scalar int
    const float* W    = (const float*)d_in[5];   // (128,32) f32
    const float* bf   = (const float*)d_in[6];   // (32,) f32
    const float* gam  = (const float*)d_in[7];   // (32,) f32
    const float* bet  = (const float*)d_in[8];   // (32,) f32
    float* out = (float*)d_out;                  // (2048,32) f32

    prep_kernel<<<N, 32>>>(feat, a, W);
    table_kernel<<<TABSZ + 1, 32>>>(a, te, bf);
    attn_kernel<<<N / ROWS, 256>>>(adj, ts, gam, bet, out);
}

// round 3
// speedup vs baseline: 2.7202x; 2.7202x over previous
#include <cuda_runtime.h>
#include <math.h>

#define N 2048
#define IN_DIM 128
#define OUT_DIM 32
#define ROWS 8
#define NWARPS 8
#define TABSZ 2048

// Scratch (allocation-free rule: __device__ globals)
__device__ float g_z[N * OUT_DIM];
__device__ float g_src[N];
__device__ float g_dst[N];
__device__ float g_val[TABSZ + 1];
__device__ float g_maxdst;
__device__ float g_maxg;

// ---------------------------------------------------------------------------
// Prep: z = feat @ W ; src = z @ a[:32] ; dst = z @ a[32:64]
// 8 warps/block, one row per warp, 4-way split accumulators.
// ---------------------------------------------------------------------------
__global__ void __launch_bounds__(256)
prep_kernel(const float* __restrict__ feat,
            const float* __restrict__ a,
            const float* __restrict__ W) {
    const int warp = threadIdx.x >> 5;
    const int lane = threadIdx.x & 31;
    const int i = blockIdx.x * 8 + warp;

    const float4* f4 = (const float4*)(feat + i * IN_DIM);
    float a0 = 0.f, a1 = 0.f, a2 = 0.f, a3 = 0.f;
#pragma unroll
    for (int d4 = 0; d4 < IN_DIM / 4; ++d4) {
        float4 f = f4[d4];  // uniform across lanes (L1 broadcast)
        a0 = fmaf(f.x, W[(d4 * 4 + 0) * OUT_DIM + lane], a0);
        a1 = fmaf(f.y, W[(d4 * 4 + 1) * OUT_DIM + lane], a1);
        a2 = fmaf(f.z, W[(d4 * 4 + 2) * OUT_DIM + lane], a2);
        a3 = fmaf(f.w, W[(d4 * 4 + 3) * OUT_DIM + lane], a3);
    }
    float acc = (a0 + a1) + (a2 + a3);
    g_z[i * OUT_DIM + lane] = acc;

    float s = acc * a[lane];
    float t = acc * a[OUT_DIM + lane];
#pragma unroll
    for (int o = 16; o > 0; o >>= 1) {
        s += __shfl_xor_sync(0xffffffffu, s, o);
        t += __shfl_xor_sync(0xffffffffu, t, o);
    }
    if (lane == 0) { g_src[i] = s; g_dst[i] = t; }
}

// ---------------------------------------------------------------------------
// Table: g_val[q] = sum_k a[2k]*sin(dt*f_k) + a[2k+1]*cos(dt*f_k),
//        dt = T - q/TABSZ. Same fp32 op sequence as reference.
// ---------------------------------------------------------------------------
__global__ void table_kernel(const float* __restrict__ a,
                             const int*   __restrict__ te,
                             const float* __restrict__ bf) {
    int q = blockIdx.x;        // 0..TABSZ
    int k = threadIdx.x;       // 0..31
    int ti = *te;
    float T = (ti > -1000000 && ti < 1000000) ? (float)ti : __int_as_float(ti);
    float tsv = (float)q / (float)TABSZ;
    float dt  = T - tsv;
    float th  = dt * bf[k];
    float v   = a[2 * k] * sinf(th) + a[2 * k + 1] * cosf(th);
#pragma unroll
    for (int o = 16; o > 0; o >>= 1)
        v += __shfl_xor_sync(0xffffffffu, v, o);
    if (k == 0) g_val[q] = v;
}

// ---------------------------------------------------------------------------
// Reduce: g_maxdst = max(dst), g_maxg = max(table). 1 block.
// ---------------------------------------------------------------------------
__global__ void __launch_bounds__(256)
reduce_kernel() {
    __shared__ float sd[8], sg[8];
    const int warp = threadIdx.x >> 5;
    const int lane = threadIdx.x & 31;
    float md = -1e30f, mg = -1e30f;
    for (int i = threadIdx.x; i < N; i += 256) md = fmaxf(md, g_dst[i]);
    for (int i = threadIdx.x; i <= TABSZ; i += 256) mg = fmaxf(mg, g_val[i]);
#pragma unroll
    for (int o = 16; o > 0; o >>= 1) {
        md = fmaxf(md, __shfl_xor_sync(0xffffffffu, md, o));
        mg = fmaxf(mg, __shfl_xor_sync(0xffffffffu, mg, o));
    }
    if (lane == 0) { sd[warp] = md; sg[warp] = mg; }
    __syncthreads();
    if (threadIdx.x == 0) {
        float a_ = -1e30f, b_ = -1e30f;
#pragma unroll
        for (int w = 0; w < 8; ++w) { a_ = fmaxf(a_, sd[w]); b_ = fmaxf(b_, sg[w]); }
        g_maxdst = a_;  g_maxg = b_;
    }
}

// ---------------------------------------------------------------------------
// Fused attention. Lane-parallel scores: each lane owns one j per batch of 32.
// Fixed softmax shift m_i = leaky(src_i + max(dst) + max(table)) (upper bound
// on every e, so exp never overflows; shift-invariance keeps result exact).
// Masked pairs: e = -1e30 -> p = 0 exactly. Branch-free hot loop.
// PV product: shfl-broadcast p across lanes, fma with z[j][lane].
// ---------------------------------------------------------------------------
__global__ void __launch_bounds__(256)
attn_kernel(const int*   __restrict__ adj,
            const float* __restrict__ ts,
            const float* __restrict__ gamma,
            const float* __restrict__ beta,
            float*       __restrict__ out) {
    __shared__ float2 s_tab[TABSZ];
    __shared__ float sm_l[ROWS][NWARPS];
    __shared__ float sm_a[ROWS][NWARPS][OUT_DIM];

    const int i0   = blockIdx.x * ROWS;
    const int warp = threadIdx.x >> 5;
    const int lane = threadIdx.x & 31;

    for (int q = threadIdx.x; q < TABSZ; q += 256)
        s_tab[q] = make_float2(g_val[q], g_val[q + 1]);
    __syncthreads();

    const float MB = g_maxdst + g_maxg;
    float src[ROWS], m[ROWS], l[ROWS], acc[ROWS];
#pragma unroll
    for (int r = 0; r < ROWS; ++r) {
        src[r] = g_src[i0 + r];
        float U = src[r] + MB;
        m[r] = fmaxf(U, 0.05f * U);   // leaky of the raw upper bound
        l[r] = 0.f;  acc[r] = 0.f;
    }

    for (int b = warp; b < N / 32; b += NWARPS) {
        const int j = b * 32 + lane;
        const float dstj = g_dst[j];
        float p[ROWS];
#pragma unroll
        for (int r = 0; r < ROWS; ++r) {
            const int   row = i0 + r;
            const int   av  = adj[row * N + j];
            const float t_  = ts [row * N + j];
            float qf = t_ * (float)TABSZ;          // ts in [0,1)
            int   qi = __float2int_rz(qf);
            float fr = qf - (float)qi;
            float2 tt = s_tab[qi];
            float g  = fmaf(fr, tt.y - tt.x, tt.x);
            float e  = src[r] + dstj + g;
            e = fmaxf(e, 0.05f * e);               // leaky relu
            e = (av > 0) ? (e - m[r]) : -1e30f;    // mask -> p = 0
            p[r] = __expf(e);
            l[r] += p[r];
        }
        const float* zb = g_z + b * 32 * OUT_DIM;
#pragma unroll
        for (int jj = 0; jj < 32; ++jj) {
            float zv = zb[jj * OUT_DIM + lane];    // coalesced 128B, L2-hit
#pragma unroll
            for (int r = 0; r < ROWS; ++r)
                acc[r] = fmaf(__shfl_sync(0xffffffffu, p[r], jj), zv, acc[r]);
        }
    }

    // Reduce l within warp; stash partials for cross-warp combine.
#pragma unroll
    for (int r = 0; r < ROWS; ++r) {
        float lv = l[r];
#pragma unroll
        for (int o = 16; o > 0; o >>= 1)
            lv += __shfl_xor_sync(0xffffffffu, lv, o);
        if (lane == 0) sm_l[r][warp] = lv;
        sm_a[r][warp][lane] = acc[r];
    }
    __syncthreads();

    // Warp r finalizes row i0+r (same m across warps -> plain sums).
    {
        const int r = warp;
        const int i = i0 + r;
        float L = 0.f, A = 0.f;
#pragma unroll
        for (int w = 0; w < NWARPS; ++w) {
            L += sm_l[r][w];
            A += sm_a[r][w][lane];
        }
        float temp = A / L + g_z[i * OUT_DIM + lane];

        float mu = temp;
#pragma unroll
        for (int o = 16; o > 0; o >>= 1) mu += __shfl_xor_sync(0xffffffffu, mu, o);
        mu *= (1.0f / OUT_DIM);
        float d = temp - mu;
        float v = d * d;
#pragma unroll
        for (int o = 16; o > 0; o >>= 1) v += __shfl_xor_sync(0xffffffffu, v, o);
        v *= (1.0f / OUT_DIM);
        out[i * OUT_DIM + lane] = d * rsqrtf(v + 1e-6f) * gamma[lane] + beta[lane];
    }
}

// ---------------------------------------------------------------------------
extern "C" void kernel_launch(void* const* d_in, const int* in_sizes, int n_in,
                              void* d_out, int out_size) {
    const float* feat = (const float*)d_in[0];   // (2048,128) f32
    const int*   adj  = (const int*)  d_in[1];   // (2048,2048) i32
    const float* ts   = (const float*)d_in[2];   // (2048,2048) f32
    const float* a    = (const float*)d_in[3];   // (64,1) f32
    const int*   te   = (const int*)  d_in[4];   // scalar int
    const float* W    = (const float*)d_in[5];   // (128,32) f32
    const float* bf   = (const float*)d_in[6];   // (32,) f32
    const float* gam  = (const float*)d_in[7];   // (32,) f32
    const float* bet  = (const float*)d_in[8];   // (32,) f32
    float* out = (float*)d_out;                  // (2048,32) f32

    prep_kernel<<<N / 8, 256>>>(feat, a, W);
    table_kernel<<<TABSZ + 1, 32>>>(a, te, bf);
    reduce_kernel<<<1, 256>>>();
    attn_kernel<<<N / ROWS, 256>>>(adj, ts, gam, bet, out);
}

// round 4
// speedup vs baseline: 4.3643x; 1.6044x over previous
#include <cuda_runtime.h>
#include <math.h>

#define N 2048
#define IN_DIM 128
#define OUT_DIM 32
#define ROWS 8
#define NWARPS 8
#define TABSZ 2048
#define JSPLIT 4
#define JCHUNK (N / JSPLIT)          // 512 j's per block
#define NBATCH (JCHUNK / 32)         // 16 batches of 32 j's

// Scratch (allocation-free rule: __device__ globals)
__device__ float g_z[N * OUT_DIM];
__device__ float g_src[N];
__device__ float g_dst[N];
__device__ float g_val[TABSZ + 1];
__device__ float g_maxdst;
__device__ float g_maxg;
__device__ float g_pl[N * JSPLIT];                 // partial softmax denominators
__device__ float g_pa[N * JSPLIT * OUT_DIM];       // partial att@z accumulators

// ---------------------------------------------------------------------------
// Prep: z = feat @ W ; src = z @ a[:32] ; dst = z @ a[32:64]
// ---------------------------------------------------------------------------
__global__ void __launch_bounds__(256)
prep_kernel(const float* __restrict__ feat,
            const float* __restrict__ a,
            const float* __restrict__ W) {
    const int warp = threadIdx.x >> 5;
    const int lane = threadIdx.x & 31;
    const int i = blockIdx.x * 8 + warp;

    const float4* f4 = (const float4*)(feat + i * IN_DIM);
    float a0 = 0.f, a1 = 0.f, a2 = 0.f, a3 = 0.f;
#pragma unroll
    for (int d4 = 0; d4 < IN_DIM / 4; ++d4) {
        float4 f = f4[d4];
        a0 = fmaf(f.x, W[(d4 * 4 + 0) * OUT_DIM + lane], a0);
        a1 = fmaf(f.y, W[(d4 * 4 + 1) * OUT_DIM + lane], a1);
        a2 = fmaf(f.z, W[(d4 * 4 + 2) * OUT_DIM + lane], a2);
        a3 = fmaf(f.w, W[(d4 * 4 + 3) * OUT_DIM + lane], a3);
    }
    float acc = (a0 + a1) + (a2 + a3);
    g_z[i * OUT_DIM + lane] = acc;

    float s = acc * a[lane];
    float t = acc * a[OUT_DIM + lane];
#pragma unroll
    for (int o = 16; o > 0; o >>= 1) {
        s += __shfl_xor_sync(0xffffffffu, s, o);
        t += __shfl_xor_sync(0xffffffffu, t, o);
    }
    if (lane == 0) { g_src[i] = s; g_dst[i] = t; }
}

// ---------------------------------------------------------------------------
// Table: g_val[q] = sum_k a[2k]*sin(dt*f_k) + a[2k+1]*cos(dt*f_k),
//        dt = T - q/TABSZ. Same fp32 op sequence as reference.
// ---------------------------------------------------------------------------
__global__ void table_kernel(const float* __restrict__ a,
                             const int*   __restrict__ te,
                             const float* __restrict__ bf) {
    int q = blockIdx.x;        // 0..TABSZ
    int k = threadIdx.x;       // 0..31
    int ti = *te;
    float T = (ti > -1000000 && ti < 1000000) ? (float)ti : __int_as_float(ti);
    float tsv = (float)q / (float)TABSZ;
    float dt  = T - tsv;
    float th  = dt * bf[k];
    float v   = a[2 * k] * sinf(th) + a[2 * k + 1] * cosf(th);
#pragma unroll
    for (int o = 16; o > 0; o >>= 1)
        v += __shfl_xor_sync(0xffffffffu, v, o);
    if (k == 0) g_val[q] = v;
}

// ---------------------------------------------------------------------------
// Reduce: g_maxdst = max(dst), g_maxg = max(table). 1 block.
// ---------------------------------------------------------------------------
__global__ void __launch_bounds__(256)
reduce_kernel() {
    __shared__ float sd[8], sg[8];
    const int warp = threadIdx.x >> 5;
    const int lane = threadIdx.x & 31;
    float md = -1e30f, mg = -1e30f;
    for (int i = threadIdx.x; i < N; i += 256) md = fmaxf(md, g_dst[i]);
    for (int i = threadIdx.x; i <= TABSZ; i += 256) mg = fmaxf(mg, g_val[i]);
#pragma unroll
    for (int o = 16; o > 0; o >>= 1) {
        md = fmaxf(md, __shfl_xor_sync(0xffffffffu, md, o));
        mg = fmaxf(mg, __shfl_xor_sync(0xffffffffu, mg, o));
    }
    if (lane == 0) { sd[warp] = md; sg[warp] = mg; }
    __syncthreads();
    if (threadIdx.x == 0) {
        float a_ = -1e30f, b_ = -1e30f;
#pragma unroll
        for (int w = 0; w < 8; ++w) { a_ = fmaxf(a_, sd[w]); b_ = fmaxf(b_, sg[w]); }
        g_maxdst = a_;  g_maxg = b_;
    }
}

// ---------------------------------------------------------------------------
// Fused attention, j-split for occupancy. grid = (N/ROWS, JSPLIT).
// Lane-parallel scores (lane = j); fixed softmax shift m_i (analytic upper
// bound -> exp in (0,1], no online rescale). PV via smem-staged p tile read
// with broadcast LDS.128 (4 rows/load) — no SHFL in the hot loop.
// Writes partial (l, acc) per (row, split) to global; combine kernel follows.
// ---------------------------------------------------------------------------
__global__ void __launch_bounds__(256)
attn_kernel(const int*   __restrict__ adj,
            const float* __restrict__ ts,
            float*       __restrict__ out_unused) {
    __shared__ float2 s_tab[TABSZ];                       // 16 KB
    __shared__ float  sm_p[NWARPS][32][ROWS];             // 8 KB
    __shared__ float  sm_l[ROWS][NWARPS];
    __shared__ float  sm_a[ROWS][NWARPS][OUT_DIM];        // 8 KB

    const int i0    = blockIdx.x * ROWS;
    const int split = blockIdx.y;
    const int jbase = split * JCHUNK;
    const int warp  = threadIdx.x >> 5;
    const int lane  = threadIdx.x & 31;

    for (int q = threadIdx.x; q < TABSZ; q += 256)
        s_tab[q] = make_float2(g_val[q], g_val[q + 1]);
    __syncthreads();

    const float MB = g_maxdst + g_maxg;
    float src[ROWS], m[ROWS], l[ROWS], acc[ROWS];
#pragma unroll
    for (int r = 0; r < ROWS; ++r) {
        src[r] = g_src[i0 + r];
        float U = src[r] + MB;
        m[r] = fmaxf(U, 0.05f * U);   // leaky of the raw upper bound
        l[r] = 0.f;  acc[r] = 0.f;
    }

    for (int bb = warp; bb < NBATCH; bb += NWARPS) {
        const int j = jbase + bb * 32 + lane;
        const float dstj = g_dst[j];
        float p[ROWS];
#pragma unroll
        for (int r = 0; r < ROWS; ++r) {
            const int   row = i0 + r;
            const int   av  = adj[row * N + j];
            const float t_  = ts [row * N + j];
            float qf = t_ * (float)TABSZ;          // ts in [0,1)
            int   qi = __float2int_rz(qf);
            float fr = qf - (float)qi;
            float2 tt = s_tab[qi];
            float g  = fmaf(fr, tt.y - tt.x, tt.x);
            float e  = src[r] + dstj + g;
            e = fmaxf(e, 0.05f * e);               // leaky relu
            e = (av > 0) ? (e - m[r]) : -1e30f;    // mask -> p = 0
            p[r] = __expf(e);
            l[r] += p[r];
        }
        // Stage p tile to smem: 2x STS.128 per lane
        float4* pd = (float4*)&sm_p[warp][lane][0];
        pd[0] = make_float4(p[0], p[1], p[2], p[3]);
        pd[1] = make_float4(p[4], p[5], p[6], p[7]);
        __syncwarp();

        const float* zb = g_z + (jbase + bb * 32) * OUT_DIM;
#pragma unroll
        for (int jj = 0; jj < 32; ++jj) {
            float zv = zb[jj * OUT_DIM + lane];    // coalesced 128B, L2-hit
            const float4* ps = (const float4*)&sm_p[warp][jj][0];
            float4 p03 = ps[0];                    // broadcast LDS.128
            float4 p47 = ps[1];
            acc[0] = fmaf(p03.x, zv, acc[0]);
            acc[1] = fmaf(p03.y, zv, acc[1]);
            acc[2] = fmaf(p03.z, zv, acc[2]);
            acc[3] = fmaf(p03.w, zv, acc[3]);
            acc[4] = fmaf(p47.x, zv, acc[4]);
            acc[5] = fmaf(p47.y, zv, acc[5]);
            acc[6] = fmaf(p47.z, zv, acc[6]);
            acc[7] = fmaf(p47.w, zv, acc[7]);
        }
        __syncwarp();
    }

    // Reduce l within warp; stash partials for cross-warp combine.
#pragma unroll
    for (int r = 0; r < ROWS; ++r) {
        float lv = l[r];
#pragma unroll
        for (int o = 16; o > 0; o >>= 1)
            lv += __shfl_xor_sync(0xffffffffu, lv, o);
        if (lane == 0) sm_l[r][warp] = lv;
        sm_a[r][warp][lane] = acc[r];
    }
    __syncthreads();

    // Warp r writes partial for row i0+r, this split.
    {
        const int r = warp;
        const int i = i0 + r;
        float L = 0.f, A = 0.f;
#pragma unroll
        for (int w = 0; w < NWARPS; ++w) {
            L += sm_l[r][w];
            A += sm_a[r][w][lane];
        }
        g_pa[(i * JSPLIT + split) * OUT_DIM + lane] = A;
        if (lane == 0) g_pl[i * JSPLIT + split] = L;
    }
}

// ---------------------------------------------------------------------------
// Combine partials + residual + layernorm. One warp per row.
// ---------------------------------------------------------------------------
__global__ void __launch_bounds__(256)
combine_kernel(const float* __restrict__ gamma,
               const float* __restrict__ beta,
               float*       __restrict__ out) {
    const int warp = threadIdx.x >> 5;
    const int lane = threadIdx.x & 31;
    const int i = blockIdx.x * 8 + warp;

    float A = 0.f, L = 0.f;
#pragma unroll
    for (int s = 0; s < JSPLIT; ++s) {
        A += g_pa[(i * JSPLIT + s) * OUT_DIM + lane];
        L += g_pl[i * JSPLIT + s];
    }
    float temp = A / L + g_z[i * OUT_DIM + lane];

    float mu = temp;
#pragma unroll
    for (int o = 16; o > 0; o >>= 1) mu += __shfl_xor_sync(0xffffffffu, mu, o);
    mu *= (1.0f / OUT_DIM);
    float d = temp - mu;
    float v = d * d;
#pragma unroll
    for (int o = 16; o > 0; o >>= 1) v += __shfl_xor_sync(0xffffffffu, v, o);
    v *= (1.0f / OUT_DIM);
    out[i * OUT_DIM + lane] = d * rsqrtf(v + 1e-6f) * gamma[lane] + beta[lane];
}

// ---------------------------------------------------------------------------
extern "C" void kernel_launch(void* const* d_in, const int* in_sizes, int n_in,
                              void* d_out, int out_size) {
    const float* feat = (const float*)d_in[0];   // (2048,128) f32
    const int*   adj  = (const int*)  d_in[1];   // (2048,2048) i32
    const float* ts   = (const float*)d_in[2];   // (2048,2048) f32
    const float* a    = (const float*)d_in[3];   // (64,1) f32
    const int*   te   = (const int*)  d_in[4];   // scalar int
    const float* W    = (const float*)d_in[5];   // (128,32) f32
    const float* bf   = (const float*)d_in[6];   // (32,) f32
    const float* gam  = (const float*)d_in[7];   // (32,) f32
    const float* bet  = (const float*)d_in[8];   // (32,) f32
    float* out = (float*)d_out;                  // (2048,32) f32

    prep_kernel<<<N / 8, 256>>>(feat, a, W);
    table_kernel<<<TABSZ + 1, 32>>>(a, te, bf);
    reduce_kernel<<<1, 256>>>();
    dim3 grid(N / ROWS, JSPLIT);
    attn_kernel<<<grid, 256>>>(adj, ts, out);
    combine_kernel<<<N / 8, 256>>>(gam, bet, out);
}

// round 5
// speedup vs baseline: 5.8668x; 1.3443x over previous
#include <cuda_runtime.h>
#include <math.h>

#define N 2048
#define IN_DIM 128
#define OUT_DIM 32
#define ROWS 8
#define NWARPS 8
#define TABSZ 1024
#define JSPLIT 4
#define JCHUNK (N / JSPLIT)          // 512 j's per block
#define NBATCH (JCHUNK / 32)         // 16 batches of 32 j's

#define PREP_BLKS (N / 8)                        // 256
#define TAB_BLKS  ((TABSZ + 1 + 7) / 8)          // 129 (8 q's per block)

// Scratch (allocation-free rule: __device__ globals)
__device__ float g_z[N * OUT_DIM];
__device__ float g_src[N];
__device__ float g_dst[N];
__device__ float g_val[TABSZ + 1];
__device__ float g_maxdst = -1e30f;   // reset by combine each run (graph-safe)
__device__ float g_maxg   = -1e30f;
__device__ float g_pl[N * JSPLIT];               // partial softmax denominators
__device__ float g_pa[N * JSPLIT * OUT_DIM];     // partial att@z accumulators

__device__ __forceinline__ float atomicMaxFloat(float* addr, float value) {
    return (value >= 0.f)
        ? __int_as_float(atomicMax((int*)addr, __float_as_int(value)))
        : __uint_as_float(atomicMin((unsigned*)addr, __float_as_uint(value)));
}

// ---------------------------------------------------------------------------
// Fused prologue. Blocks [0,256): z = feat@W, src, dst (+ dst max atomic).
// Blocks [256,385): e_time lookup table (+ table max atomic).
// ---------------------------------------------------------------------------
__global__ void __launch_bounds__(256)
prep_kernel(const float* __restrict__ feat,
            const float* __restrict__ a,
            const float* __restrict__ W,
            const int*   __restrict__ te,
            const float* __restrict__ bf) {
    const int warp = threadIdx.x >> 5;
    const int lane = threadIdx.x & 31;
    __shared__ float s_red[8];

    if (blockIdx.x < PREP_BLKS) {
        const int i = blockIdx.x * 8 + warp;
        const float4* f4 = (const float4*)(feat + i * IN_DIM);
        float a0 = 0.f, a1 = 0.f, a2 = 0.f, a3 = 0.f;
#pragma unroll
        for (int d4 = 0; d4 < IN_DIM / 4; ++d4) {
            float4 f = f4[d4];
            a0 = fmaf(f.x, W[(d4 * 4 + 0) * OUT_DIM + lane], a0);
            a1 = fmaf(f.y, W[(d4 * 4 + 1) * OUT_DIM + lane], a1);
            a2 = fmaf(f.z, W[(d4 * 4 + 2) * OUT_DIM + lane], a2);
            a3 = fmaf(f.w, W[(d4 * 4 + 3) * OUT_DIM + lane], a3);
        }
        float acc = (a0 + a1) + (a2 + a3);
        g_z[i * OUT_DIM + lane] = acc;

        float s = acc * a[lane];
        float t = acc * a[OUT_DIM + lane];
#pragma unroll
        for (int o = 16; o > 0; o >>= 1) {
            s += __shfl_xor_sync(0xffffffffu, s, o);
            t += __shfl_xor_sync(0xffffffffu, t, o);
        }
        if (lane == 0) { g_src[i] = s; g_dst[i] = t; s_red[warp] = t; }
        __syncthreads();
        if (threadIdx.x == 0) {
            float md = s_red[0];
#pragma unroll
            for (int w = 1; w < 8; ++w) md = fmaxf(md, s_red[w]);
            atomicMaxFloat(&g_maxdst, md);
        }
    } else {
        // Table: warp w computes q; 8 q's per block.
        const int q = (blockIdx.x - PREP_BLKS) * 8 + warp;
        float v = -1e30f;
        if (q <= TABSZ) {
            int ti = *te;
            float T = (ti > -1000000 && ti < 1000000) ? (float)ti
                                                      : __int_as_float(ti);
            float tsv = (float)q / (float)TABSZ;
            float dt  = T - tsv;
            float th  = dt * bf[lane];
            v = a[2 * lane] * sinf(th) + a[2 * lane + 1] * cosf(th);
#pragma unroll
            for (int o = 16; o > 0; o >>= 1)
                v += __shfl_xor_sync(0xffffffffu, v, o);
            if (lane == 0) g_val[q] = v;
        }
        if (lane == 0) s_red[warp] = v;
        __syncthreads();
        if (threadIdx.x == 0) {
            float mg = s_red[0];
#pragma unroll
            for (int w = 1; w < 8; ++w) mg = fmaxf(mg, s_red[w]);
            atomicMaxFloat(&g_maxg, mg);
        }
    }
}

// ---------------------------------------------------------------------------
// Fused attention, j-split for occupancy. grid = (N/ROWS, JSPLIT).
// Lane-parallel scores (lane = j); fixed softmax shift m_i (analytic upper
// bound -> exp in (0,1], no online rescale, branch-free). PV via smem-staged
// p tile read with broadcast LDS.128.
// ---------------------------------------------------------------------------
__global__ void __launch_bounds__(256)
attn_kernel(const int*   __restrict__ adj,
            const float* __restrict__ ts) {
    __shared__ float2 s_tab[TABSZ];                       // 8 KB
    __shared__ float  sm_p[NWARPS][32][ROWS];             // 8 KB
    __shared__ float  sm_l[ROWS][NWARPS];
    __shared__ float  sm_a[ROWS][NWARPS][OUT_DIM];        // 8 KB

    const int i0    = blockIdx.x * ROWS;
    const int split = blockIdx.y;
    const int jbase = split * JCHUNK;
    const int warp  = threadIdx.x >> 5;
    const int lane  = threadIdx.x & 31;

    for (int q = threadIdx.x; q < TABSZ; q += 256)
        s_tab[q] = make_float2(g_val[q], g_val[q + 1]);
    __syncthreads();

    const float MB = g_maxdst + g_maxg;
    float src[ROWS], m[ROWS], l[ROWS], acc[ROWS];
#pragma unroll
    for (int r = 0; r < ROWS; ++r) {
        src[r] = g_src[i0 + r];
        float U = src[r] + MB;
        m[r] = fmaxf(U, 0.05f * U);   // leaky of the raw upper bound
        l[r] = 0.f;  acc[r] = 0.f;
    }

    for (int bb = warp; bb < NBATCH; bb += NWARPS) {
        const int j = jbase + bb * 32 + lane;
        const float dstj = g_dst[j];
        float p[ROWS];
#pragma unroll
        for (int r = 0; r < ROWS; ++r) {
            const int   row = i0 + r;
            const int   av  = adj[row * N + j];
            const float t_  = ts [row * N + j];
            float qf = t_ * (float)TABSZ;          // ts in [0,1)
            int   qi = __float2int_rz(qf);
            float fr = qf - (float)qi;
            float2 tt = s_tab[qi];
            float g  = fmaf(fr, tt.y - tt.x, tt.x);
            float e  = src[r] + dstj + g;
            e = fmaxf(e, 0.05f * e);               // leaky relu
            e = (av > 0) ? (e - m[r]) : -1e30f;    // mask -> p = 0
            p[r] = __expf(e);
            l[r] += p[r];
        }
        // Stage p tile to smem: 2x STS.128 per lane
        float4* pd = (float4*)&sm_p[warp][lane][0];
        pd[0] = make_float4(p[0], p[1], p[2], p[3]);
        pd[1] = make_float4(p[4], p[5], p[6], p[7]);
        __syncwarp();

        const float* zb = g_z + (jbase + bb * 32) * OUT_DIM;
#pragma unroll
        for (int jj = 0; jj < 32; ++jj) {
            float zv = zb[jj * OUT_DIM + lane];    // coalesced 128B, L2-hit
            const float4* ps = (const float4*)&sm_p[warp][jj][0];
            float4 p03 = ps[0];                    // broadcast LDS.128
            float4 p47 = ps[1];
            acc[0] = fmaf(p03.x, zv, acc[0]);
            acc[1] = fmaf(p03.y, zv, acc[1]);
            acc[2] = fmaf(p03.z, zv, acc[2]);
            acc[3] = fmaf(p03.w, zv, acc[3]);
            acc[4] = fmaf(p47.x, zv, acc[4]);
            acc[5] = fmaf(p47.y, zv, acc[5]);
            acc[6] = fmaf(p47.z, zv, acc[6]);
            acc[7] = fmaf(p47.w, zv, acc[7]);
        }
        __syncwarp();
    }

    // Reduce l within warp; stash partials for cross-warp combine.
#pragma unroll
    for (int r = 0; r < ROWS; ++r) {
        float lv = l[r];
#pragma unroll
        for (int o = 16; o > 0; o >>= 1)
            lv += __shfl_xor_sync(0xffffffffu, lv, o);
        if (lane == 0) sm_l[r][warp] = lv;
        sm_a[r][warp][lane] = acc[r];
    }
    __syncthreads();

    // Warp r writes partial for row i0+r, this split.
    {
        const int r = warp;
        const int i = i0 + r;
        float L = 0.f, A = 0.f;
#pragma unroll
        for (int w = 0; w < NWARPS; ++w) {
            L += sm_l[r][w];
            A += sm_a[r][w][lane];
        }
        g_pa[(i * JSPLIT + split) * OUT_DIM + lane] = A;
        if (lane == 0) g_pl[i * JSPLIT + split] = L;
    }
}

// ---------------------------------------------------------------------------
// Combine partials + residual + layernorm. One warp per row.
// Also resets the max cells for the next graph replay.
// ---------------------------------------------------------------------------
__global__ void __launch_bounds__(256)
combine_kernel(const float* __restrict__ gamma,
               const float* __restrict__ beta,
               float*       __restrict__ out) {
    const int warp = threadIdx.x >> 5;
    const int lane = threadIdx.x & 31;
    const int i = blockIdx.x * 8 + warp;

    float A = 0.f, L = 0.f;
#pragma unroll
    for (int s = 0; s < JSPLIT; ++s) {
        A += g_pa[(i * JSPLIT + s) * OUT_DIM + lane];
        L += g_pl[i * JSPLIT + s];
    }
    float temp = A / L + g_z[i * OUT_DIM + lane];

    float mu = temp;
#pragma unroll
    for (int o = 16; o > 0; o >>= 1) mu += __shfl_xor_sync(0xffffffffu, mu, o);
    mu *= (1.0f / OUT_DIM);
    float d = temp - mu;
    float v = d * d;
#pragma unroll
    for (int o = 16; o > 0; o >>= 1) v += __shfl_xor_sync(0xffffffffu, v, o);
    v *= (1.0f / OUT_DIM);
    out[i * OUT_DIM + lane] = d * rsqrtf(v + 1e-6f) * gamma[lane] + beta[lane];

    if (blockIdx.x == 0 && threadIdx.x == 0) {
        g_maxdst = -1e30f;      // reset for next replay (deterministic)
        g_maxg   = -1e30f;
    }
}

// ---------------------------------------------------------------------------
extern "C" void kernel_launch(void* const* d_in, const int* in_sizes, int n_in,
                              void* d_out, int out_size) {
    const float* feat = (const float*)d_in[0];   // (2048,128) f32
    const int*   adj  = (const int*)  d_in[1];   // (2048,2048) i32
    const float* ts   = (const float*)d_in[2];   // (2048,2048) f32
    const float* a    = (const float*)d_in[3];   // (64,1) f32
    const int*   te   = (const int*)  d_in[4];   // scalar int
    const float* W    = (const float*)d_in[5];   // (128,32) f32
    const float* bf   = (const float*)d_in[6];   // (32,) f32
    const float* gam  = (const float*)d_in[7];   // (32,) f32
    const float* bet  = (const float*)d_in[8];   // (32,) f32
    float* out = (float*)d_out;                  // (2048,32) f32

    prep_kernel<<<PREP_BLKS + TAB_BLKS, 256>>>(feat, a, W, te, bf);
    dim3 grid(N / ROWS, JSPLIT);
    attn_kernel<<<grid, 256>>>(adj, ts);
    combine_kernel<<<N / 8, 256>>>(gam, bet, out);
}